// round 5
// baseline (speedup 1.0000x reference)
#include <cuda_runtime.h>
#include <math.h>

#define B   16
#define TK  2048
#define STK 64
#define N   512

// output layout (flattened tuple, row-major each)
#define OFF_CT    0
#define OFF_ATTN  (B*N)
#define OFF_COV   (OFF_ATTN + B*TK)
#define OFF_SCT   (OFF_COV + B*TK)
#define OFF_SATTN (OFF_SCT + B*N)

// scratch
__device__ float g_dec[B*N];       // word decoder features
__device__ float g_sdec[B*N];      // sentence decoder features
__device__ float g_e[B*TK];        // exp(score)*mask
__device__ float g_S[B];           // sum of e per b
__device__ float g_segsum[B*STK];  // per-sentence sums of e

__device__ __forceinline__ float warp_sum(float v)
{
#pragma unroll
    for (int o = 16; o; o >>= 1) v += __shfl_xor_sync(0xffffffffu, v, o);
    return v;
}
__device__ __forceinline__ float warp_max(float v)
{
#pragma unroll
    for (int o = 16; o; o >>= 1) v = fmaxf(v, __shfl_xor_sync(0xffffffffu, v, o));
    return v;
}
__device__ __forceinline__ float dot4(float4 a, float4 b)
{
    return fmaf(a.x, b.x, fmaf(a.y, b.y, fmaf(a.z, b.z, a.w * b.w)));
}
__device__ __forceinline__ float tanh_fast(float x)
{
    float y;
    asm("tanh.approx.f32 %0, %1;" : "=f"(y) : "f"(x));
    return y;
}

__device__ __forceinline__ int seg_of(int t, const int* pos)
{
    // count of pos[i] <= t  (searchsorted side='right')
    int lo = 0, hi = STK;
    while (lo < hi) {
        int mid = (lo + hi) >> 1;
        if (pos[mid] <= t) lo = mid + 1; else hi = mid;
    }
    return lo;
}

// ---------------------------------------------------------------------------
// Kernel 1: both dec GEMMs, full-chip parallel.
// grid 512, 256 thr (8 warps). Each block: 2 rows x 4 b-groups.
// Also zeroes g_S, g_segsum, o_ct (distributed).
// ---------------------------------------------------------------------------
__global__ void dec_gemm(const float* __restrict__ s_word,
                         const float* __restrict__ Wd,
                         const float* __restrict__ bd,
                         const float* __restrict__ s_sent,
                         const float* __restrict__ Wsd,
                         const float* __restrict__ bsd,
                         float* __restrict__ o_ct)
{
    int blk  = blockIdx.x;            // 0..511
    int tid  = threadIdx.x;
    int wid  = tid >> 5;
    int lane = tid & 31;

    // distributed zeroing
    int g = blk * 256 + tid;
    if (g < B * N)   o_ct[g] = 0.f;
    if (g < B * STK) g_segsum[g] = 0.f;
    if (g < B)       g_S[g] = 0.f;

    int which = blk >> 8;             // 0 word, 1 sentence
    int rem   = blk & 255;
    const float* W    = which ? Wsd    : Wd;
    const float* bias = which ? bsd    : bd;
    const float* s    = which ? s_sent : s_word;
    float*       dst  = which ? g_sdec : g_dec;

    int n  = rem * 2 + (wid >> 2);    // row index 0..511
    int b0 = (wid & 3) * 4;           // batch group

    const float4* wv = (const float4*)(W + (size_t)n * N);
    float4 w0 = wv[lane], w1 = wv[32 + lane], w2 = wv[64 + lane], w3 = wv[96 + lane];
    float bn = bias[n];

#pragma unroll
    for (int bb = 0; bb < 4; bb++) {
        int b = b0 + bb;
        const float4* sv = (const float4*)(s + (size_t)b * N);
        float acc = dot4(sv[lane], w0) + dot4(sv[32 + lane], w1)
                  + dot4(sv[64 + lane], w2) + dot4(sv[96 + lane], w3);
        acc = warp_sum(acc);
        if (lane == 0) dst[b * N + n] = acc + bn;
    }
}

// ---------------------------------------------------------------------------
// Kernel 2 (fused): blocks 0-4095: 8 tokens of one b.
//   Phase A: e = exp(score)*mask (warp per token), atomic segsum + per-b S.
//   Phase B: unnormalized context: c_hat[b,n] += sum_t e_t * enc[b,t,n]
//            (threads 0-127 tokens 0-3, threads 128-255 tokens 4-7).
// blocks 4096-4111: full sentence path for b.
// ---------------------------------------------------------------------------
__global__ void score_ctx(const float* __restrict__ feat,
                          const float* __restrict__ enc,
                          const float* __restrict__ v,
                          const float* __restrict__ wc,
                          const float* __restrict__ cov,
                          const float* __restrict__ mask,
                          const int* __restrict__ spos,
                          const float* __restrict__ sfeat,
                          const float* __restrict__ svw,
                          const float* __restrict__ smask,
                          const float* __restrict__ sout,
                          float* __restrict__ o_sattn,
                          float* __restrict__ o_sct,
                          float* __restrict__ o_ct)
{
    int blk  = blockIdx.x;
    int tid  = threadIdx.x;
    int wid  = tid >> 5;
    int lane = tid & 31;

    if (blk < 4096) {
        __shared__ int   pos[STK];
        __shared__ float e_sh[8];

        int b  = blk >> 8;              // 256 blocks per b
        int t0 = (blk & 255) * 8;

        if (tid < STK) pos[tid] = spos[b * STK + tid];
        __syncthreads();

        // ---- Phase A: score for token t0+wid ----
        int t = t0 + wid;
        int gidx = b * TK + t;
        float c = cov[gidx];
        const float4* fv = (const float4*)(feat + (size_t)gidx * N);
        const float4* dv = (const float4*)(g_dec + (size_t)b * N);
        const float4* vv = (const float4*)v;
        const float4* wv = (const float4*)wc;

        float acc = 0.f;
#pragma unroll
        for (int i = 0; i < 4; i++) {
            int j = i * 32 + lane;
            float4 f = fv[j];
            float4 d = dv[j];
            float4 V = vv[j];
            float4 w = wv[j];
            acc = fmaf(tanh_fast(f.x + d.x + c * w.x), V.x,
                  fmaf(tanh_fast(f.y + d.y + c * w.y), V.y,
                  fmaf(tanh_fast(f.z + d.z + c * w.z), V.z,
                  fmaf(tanh_fast(f.w + d.w + c * w.w), V.w, acc))));
        }
        acc = warp_sum(acc);

        if (lane == 0) {
            float e = expf(acc) * mask[gidx];
            g_e[gidx] = e;
            int sg = seg_of(t, pos);
            if (sg < STK) atomicAdd(&g_segsum[b * STK + sg], e);
            e_sh[wid] = e;
        }
        __syncthreads();
        if (tid == 0) {
            float s = 0.f;
#pragma unroll
            for (int i = 0; i < 8; i++) s += e_sh[i];
            atomicAdd(&g_S[b], s);
        }

        // ---- Phase B: weighted context for these 8 tokens ----
        int half = tid >> 7;            // 0: tokens 0-3, 1: tokens 4-7
        int n4   = tid & 127;           // float4 index in N
        const float4* ev = (const float4*)enc;
        size_t base = ((size_t)b * TK + t0 + half * 4) * (N / 4) + n4;
        float4 a4 = make_float4(0.f, 0.f, 0.f, 0.f);
#pragma unroll
        for (int i = 0; i < 4; i++) {
            float e = e_sh[half * 4 + i];
            float4 x = ev[base + (size_t)i * (N / 4)];
            a4.x = fmaf(e, x.x, a4.x);
            a4.y = fmaf(e, x.y, a4.y);
            a4.z = fmaf(e, x.z, a4.z);
            a4.w = fmaf(e, x.w, a4.w);
        }
        float* o = o_ct + (size_t)b * N + n4 * 4;
        atomicAdd(o + 0, a4.x);
        atomicAdd(o + 1, a4.y);
        atomicAdd(o + 2, a4.z);
        atomicAdd(o + 3, a4.w);
    } else {
        // ---------------- sentence path: one block per b ----------------
        __shared__ float se[STK];
        int b = blk - 4096;

        const float4* dv = (const float4*)(g_sdec + (size_t)b * N);
        const float4* vv = (const float4*)svw;
        for (int t = wid; t < STK; t += 8) {
            const float4* fv = (const float4*)(sfeat + ((size_t)b * STK + t) * N);
            float acc = 0.f;
#pragma unroll
            for (int i = 0; i < 4; i++) {
                int j = i * 32 + lane;
                float4 f = fv[j];
                float4 d = dv[j];
                float4 V = vv[j];
                acc = fmaf(tanh_fast(f.x + d.x), V.x,
                      fmaf(tanh_fast(f.y + d.y), V.y,
                      fmaf(tanh_fast(f.z + d.z), V.z,
                      fmaf(tanh_fast(f.w + d.w), V.w, acc))));
            }
            acc = warp_sum(acc);
            if (lane == 0) se[t] = acc;
        }
        __syncthreads();

        // softmax + mask renorm (warp 0, 2 elems per lane)
        if (wid == 0) {
            float s0 = se[lane], s1 = se[lane + 32];
            float m = warp_max(fmaxf(s0, s1));
            float e0 = expf(s0 - m), e1 = expf(s1 - m);
            float inv = 1.f / warp_sum(e0 + e1);
            float a0 = e0 * inv * smask[b * STK + lane];
            float a1 = e1 * inv * smask[b * STK + 32 + lane];
            float inv2 = 1.f / warp_sum(a0 + a1);
            a0 *= inv2; a1 *= inv2;
            se[lane] = a0; se[lane + 32] = a1;
            o_sattn[b * STK + lane]      = a0;
            o_sattn[b * STK + 32 + lane] = a1;
        }
        __syncthreads();

        // sentence context
        for (int n = tid; n < N; n += 256) {
            float acc = 0.f;
#pragma unroll 8
            for (int t = 0; t < STK; t++)
                acc = fmaf(se[t], sout[((size_t)b * STK + t) * N + n], acc);
            o_sct[b * N + n] = acc;
        }
    }
}

// ---------------------------------------------------------------------------
// Kernel 3: finalize. grid 64, 512 thr.
//   Every block: 512 tokens of one b (4 blocks per b): attn = e/S,
//   coverage = cov + e/segsum*sattn.
//   Blocks 0-15 additionally scale c_t by 1/S.
// ---------------------------------------------------------------------------
__global__ void finalize(const float* __restrict__ cov,
                         const int* __restrict__ spos,
                         const float* __restrict__ sattn,
                         float* __restrict__ o_attn,
                         float* __restrict__ o_cov,
                         float* __restrict__ o_ct)
{
    __shared__ int   pos[STK];
    __shared__ float ssum[STK];
    __shared__ float satt[STK];

    int blk = blockIdx.x;           // 64 blocks
    int b   = blk >> 2;
    int t0  = (blk & 3) * 512;
    int tid = threadIdx.x;

    if (tid < STK) {
        pos[tid]  = spos[b * STK + tid];
        ssum[tid] = g_segsum[b * STK + tid];
        satt[tid] = sattn[b * STK + tid];
    }
    __syncthreads();

    float invS = 1.f / g_S[b];

    int t = t0 + tid;
    float e = g_e[b * TK + t];
    o_attn[b * TK + t] = e * invS;
    int sg = seg_of(t, pos);
    float sw = (sg < STK) ? e / ssum[sg] * satt[sg] : 0.f;
    o_cov[b * TK + t] = cov[b * TK + t] + sw;

    if ((blk & 3) == 0)             // one block per b scales c_t
        o_ct[b * N + tid] *= invS;
}

// ---------------------------------------------------------------------------
extern "C" void kernel_launch(void* const* d_in, const int* in_sizes, int n_in,
                              void* d_out, int out_size)
{
    const float* s_t_hat  = (const float*)d_in[0];
    const int*   spos     = (const int*)  d_in[1];
    const float* enc_out  = (const float*)d_in[2];
    const float* enc_feat = (const float*)d_in[3];
    const float* mask     = (const float*)d_in[4];
    const float* s_sent   = (const float*)d_in[5];
    const float* sout     = (const float*)d_in[6];
    const float* sfeat    = (const float*)d_in[7];
    const float* smask    = (const float*)d_in[8];
    const float* cov      = (const float*)d_in[9];
    const float* Wd       = (const float*)d_in[10];
    const float* bd       = (const float*)d_in[11];
    const float* vw       = (const float*)d_in[12];
    const float* Wsd      = (const float*)d_in[13];
    const float* bsd      = (const float*)d_in[14];
    const float* svw      = (const float*)d_in[15];
    const float* wc       = (const float*)d_in[16];

    float* out     = (float*)d_out;
    float* o_ct    = out + OFF_CT;
    float* o_attn  = out + OFF_ATTN;
    float* o_cov   = out + OFF_COV;
    float* o_sct   = out + OFF_SCT;
    float* o_sattn = out + OFF_SATTN;

    dec_gemm<<<512, 256>>>(s_t_hat, Wd, bd, s_sent, Wsd, bsd, o_ct);

    score_ctx<<<4096 + 16, 256>>>(enc_feat, enc_out, vw, wc, cov, mask, spos,
                                  sfeat, svw, smask, sout, o_sattn, o_sct, o_ct);

    finalize<<<64, 512>>>(cov, spos, o_sattn, o_attn, o_cov, o_ct);
}

// round 6
// speedup vs baseline: 2.2955x; 2.2955x over previous
#include <cuda_runtime.h>
#include <math.h>

#define B   16
#define TK  2048
#define STK 64
#define N   512

// output layout (flattened tuple, row-major each)
#define OFF_CT    0
#define OFF_ATTN  (B*N)
#define OFF_COV   (OFF_ATTN + B*TK)
#define OFF_SCT   (OFF_COV + B*TK)
#define OFF_SATTN (OFF_SCT + B*N)

// scratch
__device__ float g_dec[B*N];       // word decoder features
__device__ float g_sdec[B*N];      // sentence decoder features
__device__ float g_e[B*TK];        // exp(score)*mask
__device__ float g_S[B];           // sum of e per b
__device__ float g_segsum[B*STK];  // per-sentence sums of e

__device__ __forceinline__ float warp_sum(float v)
{
#pragma unroll
    for (int o = 16; o; o >>= 1) v += __shfl_xor_sync(0xffffffffu, v, o);
    return v;
}
__device__ __forceinline__ float warp_max(float v)
{
#pragma unroll
    for (int o = 16; o; o >>= 1) v = fmaxf(v, __shfl_xor_sync(0xffffffffu, v, o));
    return v;
}
__device__ __forceinline__ float dot4(float4 a, float4 b)
{
    return fmaf(a.x, b.x, fmaf(a.y, b.y, fmaf(a.z, b.z, a.w * b.w)));
}
__device__ __forceinline__ float tanh_fast(float x)
{
    float y;
    asm("tanh.approx.f32 %0, %1;" : "=f"(y) : "f"(x));
    return y;
}

__device__ __forceinline__ int seg_of(int t, const int* pos)
{
    // count of pos[i] <= t  (searchsorted side='right')
    int lo = 0, hi = STK;
    while (lo < hi) {
        int mid = (lo + hi) >> 1;
        if (pos[mid] <= t) lo = mid + 1; else hi = mid;
    }
    return lo;
}

// ---------------------------------------------------------------------------
// Kernel 1: both dec GEMMs, full-chip parallel.
// grid 512, 256 thr (8 warps). Each block: 2 rows x 4 b-groups.
// Also zeroes g_S, g_segsum, o_ct (distributed).
// ---------------------------------------------------------------------------
__global__ void dec_gemm(const float* __restrict__ s_word,
                         const float* __restrict__ Wd,
                         const float* __restrict__ bd,
                         const float* __restrict__ s_sent,
                         const float* __restrict__ Wsd,
                         const float* __restrict__ bsd,
                         float* __restrict__ o_ct)
{
    int blk  = blockIdx.x;            // 0..511
    int tid  = threadIdx.x;
    int wid  = tid >> 5;
    int lane = tid & 31;

    // distributed zeroing
    int g = blk * 256 + tid;
    if (g < B * N)   o_ct[g] = 0.f;
    if (g < B * STK) g_segsum[g] = 0.f;
    if (g < B)       g_S[g] = 0.f;

    int which = blk >> 8;             // 0 word, 1 sentence
    int rem   = blk & 255;
    const float* W    = which ? Wsd    : Wd;
    const float* bias = which ? bsd    : bd;
    const float* s    = which ? s_sent : s_word;
    float*       dst  = which ? g_sdec : g_dec;

    int n  = rem * 2 + (wid >> 2);    // row index 0..511
    int b0 = (wid & 3) * 4;           // batch group

    const float4* wv = (const float4*)(W + (size_t)n * N);
    float4 w0 = wv[lane], w1 = wv[32 + lane], w2 = wv[64 + lane], w3 = wv[96 + lane];
    float bn = bias[n];

#pragma unroll
    for (int bb = 0; bb < 4; bb++) {
        int b = b0 + bb;
        const float4* sv = (const float4*)(s + (size_t)b * N);
        float acc = dot4(sv[lane], w0) + dot4(sv[32 + lane], w1)
                  + dot4(sv[64 + lane], w2) + dot4(sv[96 + lane], w3);
        acc = warp_sum(acc);
        if (lane == 0) dst[b * N + n] = acc + bn;
    }
}

// ---------------------------------------------------------------------------
// Kernel 2: blocks 0-1023: 32 tokens of one b; warp handles 4 tokens with
//           dec/v/wc slices resident in registers (loaded once per warp).
//           e = exp(score)*mask, atomic segsum + per-b S.
//           blocks 1024-1039: full sentence path for b.
// ---------------------------------------------------------------------------
__global__ void score_big(const float* __restrict__ feat,
                          const float* __restrict__ v,
                          const float* __restrict__ wc,
                          const float* __restrict__ cov,
                          const float* __restrict__ mask,
                          const int* __restrict__ spos,
                          const float* __restrict__ sfeat,
                          const float* __restrict__ svw,
                          const float* __restrict__ smask,
                          const float* __restrict__ sout,
                          float* __restrict__ o_sattn,
                          float* __restrict__ o_sct)
{
    int blk  = blockIdx.x;
    int tid  = threadIdx.x;
    int wid  = tid >> 5;
    int lane = tid & 31;

    if (blk < 1024) {
        __shared__ int   pos[STK];
        __shared__ float warp_e[8];

        int b  = blk >> 6;              // 64 blocks per b
        int t0 = (blk & 63) * 32;       // 32 tokens per block, warp owns 4

        if (tid < STK) pos[tid] = spos[b * STK + tid];
        __syncthreads();

        // token-invariant operand slices -> registers (once per warp)
        const float4* dv = (const float4*)(g_dec + (size_t)b * N);
        const float4* vv = (const float4*)v;
        const float4* wv = (const float4*)wc;
        float4 d0 = dv[lane], d1 = dv[32 + lane], d2 = dv[64 + lane], d3 = dv[96 + lane];
        float4 V0 = vv[lane], V1 = vv[32 + lane], V2 = vv[64 + lane], V3 = vv[96 + lane];
        float4 c0 = wv[lane], c1 = wv[32 + lane], c2 = wv[64 + lane], c3 = wv[96 + lane];

        float esum = 0.f;
#pragma unroll
        for (int tt = 0; tt < 4; tt++) {
            int t = t0 + wid * 4 + tt;
            int gidx = b * TK + t;
            float c = cov[gidx];
            const float4* fv = (const float4*)(feat + (size_t)gidx * N);
            float4 f0 = fv[lane], f1 = fv[32 + lane], f2 = fv[64 + lane], f3 = fv[96 + lane];

            float acc;
            acc = fmaf(tanh_fast(f0.x + d0.x + c * c0.x), V0.x,
                  fmaf(tanh_fast(f0.y + d0.y + c * c0.y), V0.y,
                  fmaf(tanh_fast(f0.z + d0.z + c * c0.z), V0.z,
                       tanh_fast(f0.w + d0.w + c * c0.w) * V0.w)));
            acc = fmaf(tanh_fast(f1.x + d1.x + c * c1.x), V1.x,
                  fmaf(tanh_fast(f1.y + d1.y + c * c1.y), V1.y,
                  fmaf(tanh_fast(f1.z + d1.z + c * c1.z), V1.z,
                  fmaf(tanh_fast(f1.w + d1.w + c * c1.w), V1.w, acc))));
            acc = fmaf(tanh_fast(f2.x + d2.x + c * c2.x), V2.x,
                  fmaf(tanh_fast(f2.y + d2.y + c * c2.y), V2.y,
                  fmaf(tanh_fast(f2.z + d2.z + c * c2.z), V2.z,
                  fmaf(tanh_fast(f2.w + d2.w + c * c2.w), V2.w, acc))));
            acc = fmaf(tanh_fast(f3.x + d3.x + c * c3.x), V3.x,
                  fmaf(tanh_fast(f3.y + d3.y + c * c3.y), V3.y,
                  fmaf(tanh_fast(f3.z + d3.z + c * c3.z), V3.z,
                  fmaf(tanh_fast(f3.w + d3.w + c * c3.w), V3.w, acc))));
            acc = warp_sum(acc);

            if (lane == 0) {
                float e = expf(acc) * mask[gidx];
                g_e[gidx] = e;
                int sg = seg_of(t, pos);
                if (sg < STK) atomicAdd(&g_segsum[b * STK + sg], e);
                esum += e;
            }
        }
        if (lane == 0) warp_e[wid] = esum;
        __syncthreads();
        if (tid == 0) {
            float s = 0.f;
#pragma unroll
            for (int i = 0; i < 8; i++) s += warp_e[i];
            atomicAdd(&g_S[b], s);
        }
    } else {
        // ---------------- sentence path: one block per b ----------------
        __shared__ float se[STK];
        int b = blk - 1024;

        const float4* dv = (const float4*)(g_sdec + (size_t)b * N);
        const float4* vv = (const float4*)svw;
        for (int t = wid; t < STK; t += 8) {
            const float4* fv = (const float4*)(sfeat + ((size_t)b * STK + t) * N);
            float acc = 0.f;
#pragma unroll
            for (int i = 0; i < 4; i++) {
                int j = i * 32 + lane;
                float4 f = fv[j];
                float4 d = dv[j];
                float4 V = vv[j];
                acc = fmaf(tanh_fast(f.x + d.x), V.x,
                      fmaf(tanh_fast(f.y + d.y), V.y,
                      fmaf(tanh_fast(f.z + d.z), V.z,
                      fmaf(tanh_fast(f.w + d.w), V.w, acc))));
            }
            acc = warp_sum(acc);
            if (lane == 0) se[t] = acc;
        }
        __syncthreads();

        // softmax + mask renorm (warp 0, 2 elems per lane)
        if (wid == 0) {
            float s0 = se[lane], s1 = se[lane + 32];
            float m = warp_max(fmaxf(s0, s1));
            float e0 = expf(s0 - m), e1 = expf(s1 - m);
            float inv = 1.f / warp_sum(e0 + e1);
            float a0 = e0 * inv * smask[b * STK + lane];
            float a1 = e1 * inv * smask[b * STK + 32 + lane];
            float inv2 = 1.f / warp_sum(a0 + a1);
            a0 *= inv2; a1 *= inv2;
            se[lane] = a0; se[lane + 32] = a1;
            o_sattn[b * STK + lane]      = a0;
            o_sattn[b * STK + 32 + lane] = a1;
        }
        __syncthreads();

        // sentence context
        for (int n = tid; n < N; n += 256) {
            float acc = 0.f;
#pragma unroll 8
            for (int t = 0; t < STK; t++)
                acc = fmaf(se[t], sout[((size_t)b * STK + t) * N + n], acc);
            o_sct[b * N + n] = acc;
        }
    }
}

// ---------------------------------------------------------------------------
// Kernel 3: finalize attention (attn, coverage) + word context reduction.
// grid (B, 64), 128 threads. Each block handles 32 tokens; threads own
// a float4 slice of N; atomicAdd partial c_t.
// ---------------------------------------------------------------------------
#define TSPLIT 64
#define TCHUNK (TK / TSPLIT)   // 32

__global__ void ctx_big(const float* __restrict__ enc,
                        const float* __restrict__ cov,
                        const int* __restrict__ spos,
                        const float* __restrict__ sattn,
                        float* __restrict__ o_attn,
                        float* __restrict__ o_cov,
                        float* __restrict__ o_ct)
{
    __shared__ float sh_a[TCHUNK];
    __shared__ int   pos[STK];
    __shared__ float ssum[STK];
    __shared__ float satt[STK];

    int b  = blockIdx.x, sp = blockIdx.y;
    int t0 = sp * TCHUNK;
    int tid = threadIdx.x;   // 128

    if (tid < STK) {
        pos[tid]  = spos[b * STK + tid];
        ssum[tid] = g_segsum[b * STK + tid];
        satt[tid] = sattn[b * STK + tid];
    }
    __syncthreads();

    if (tid < TCHUNK) {
        int t = t0 + tid;
        float e = g_e[b * TK + t];
        float a = e / g_S[b];
        sh_a[tid] = a;
        o_attn[b * TK + t] = a;
        int sg = seg_of(t, pos);
        float sw = (sg < STK) ? e / ssum[sg] * satt[sg] : 0.f;
        o_cov[b * TK + t] = cov[b * TK + t] + sw;
    }
    __syncthreads();

    const float4* ev = (const float4*)enc;
    size_t base = ((size_t)b * TK + t0) * (N / 4) + tid;
    float4 acc = make_float4(0.f, 0.f, 0.f, 0.f);
#pragma unroll 8
    for (int i = 0; i < TCHUNK; i++) {
        float a = sh_a[i];
        float4 x = ev[base + (size_t)i * (N / 4)];
        acc.x = fmaf(a, x.x, acc.x);
        acc.y = fmaf(a, x.y, acc.y);
        acc.z = fmaf(a, x.z, acc.z);
        acc.w = fmaf(a, x.w, acc.w);
    }
    float* o = o_ct + (size_t)b * N + tid * 4;
    atomicAdd(o + 0, acc.x);
    atomicAdd(o + 1, acc.y);
    atomicAdd(o + 2, acc.z);
    atomicAdd(o + 3, acc.w);
}

// ---------------------------------------------------------------------------
extern "C" void kernel_launch(void* const* d_in, const int* in_sizes, int n_in,
                              void* d_out, int out_size)
{
    const float* s_t_hat  = (const float*)d_in[0];
    const int*   spos     = (const int*)  d_in[1];
    const float* enc_out  = (const float*)d_in[2];
    const float* enc_feat = (const float*)d_in[3];
    const float* mask     = (const float*)d_in[4];
    const float* s_sent   = (const float*)d_in[5];
    const float* sout     = (const float*)d_in[6];
    const float* sfeat    = (const float*)d_in[7];
    const float* smask    = (const float*)d_in[8];
    const float* cov      = (const float*)d_in[9];
    const float* Wd       = (const float*)d_in[10];
    const float* bd       = (const float*)d_in[11];
    const float* vw       = (const float*)d_in[12];
    const float* Wsd      = (const float*)d_in[13];
    const float* bsd      = (const float*)d_in[14];
    const float* svw      = (const float*)d_in[15];
    const float* wc       = (const float*)d_in[16];

    float* out     = (float*)d_out;
    float* o_ct    = out + OFF_CT;
    float* o_attn  = out + OFF_ATTN;
    float* o_cov   = out + OFF_COV;
    float* o_sct   = out + OFF_SCT;
    float* o_sattn = out + OFF_SATTN;

    dec_gemm<<<512, 256>>>(s_t_hat, Wd, bd, s_sent, Wsd, bsd, o_ct);

    score_big<<<1024 + 16, 256>>>(enc_feat, vw, wc, cov, mask, spos,
                                  sfeat, svw, smask, sout, o_sattn, o_sct);

    ctx_big<<<dim3(B, TSPLIT), 128>>>(enc_out, cov, spos, o_sattn,
                                      o_attn, o_cov, o_ct);
}